// round 17
// baseline (speedup 1.0000x reference)
#include <cuda_runtime.h>
#include <math.h>

#define NC 128   // clusters
#define ND 64    // dimension
#define NPAIRS (NC * (NC - 1) / 2)   // 8128 upper-triangle pairs

// V_FACTOR = 2*pi^32/(64*31!) — reference multiplies det by this in fp32; the
// product underflows (FTZ -> 0) for tiny dets, which drives the validity mask.
#define V_FACTOR_D 3.080513e-20
#define FLT_MIN_NORMAL 1.1754943508222875e-38

// ---------------- device scratch (no allocations allowed) ----------------
static __device__ __align__(16) float g_mu[NC * ND];
static __device__ __align__(16) float g_Smod[ND * ND];   // the one mutated S row
static __device__ __align__(16) float g_ZZ[NC * ND * ND];
static __device__ float  g_n[NC];
static __device__ float  g_Gamma[NC];
static __device__ float  g_Vii32[NC];
static __device__ float  g_kappa[NC * NC];
static __device__ int    g_active[NC];
static __device__ int    g_sel[NC];
static __device__ int    g_modidx;
static __device__ int    g_kmin_key;     // order-preserving int key of min kappa

__device__ __forceinline__ float  f_inf() { return __int_as_float(0x7f800000); }
__device__ __forceinline__ double d_inf() { return __longlong_as_double(0x7ff0000000000000LL); }

__device__ __forceinline__ int f2key(float f) {
    int b = __float_as_int(f);
    return (b >= 0) ? b : (int)(~(unsigned)b);
}
__device__ __forceinline__ float key2f(int k) {
    return __int_as_float((k >= 0) ? k : (int)(~(unsigned)k));
}

// Emulate the reference's fp32 `V_ij = V_FACTOR*det > 0` test under FTZ.
__device__ __forceinline__ bool vij_valid(double det) {
    return (det > 0.0) && (det * V_FACTOR_D >= FLT_MIN_NORMAL);
}

// ---------------------------------------------------------------------------
// fp32 64x64 forward elimination (128-thread row engine) — used by k23.
// s_piv MUST be 16B-aligned (float4 access).
// ---------------------------------------------------------------------------
__device__ __forceinline__ void block_elim64f(float a[32], float* s_piv, float* s_pk) {
    const int tid  = threadIdx.x;
    const int row  = tid >> 1;
    const int half = tid & 1;
    const int c0   = half << 5;
    if (row == 0) {
#pragma unroll
        for (int q = 0; q < 8; ++q)
            reinterpret_cast<float4*>(s_piv)[half * 8 + q] =
                make_float4(a[4*q], a[4*q+1], a[4*q+2], a[4*q+3]);
    }
    __syncthreads();
#pragma unroll
    for (int k = 0; k < 64; ++k) {
        const float* buf = s_piv + ((k & 1) << 6);
        float pk = buf[k];
        if (tid == 0) s_pk[k] = pk;
        float cand  = a[k & 31];
        float other = __shfl_xor_sync(0xffffffffu, cand, 1);
        float fr    = ((k >> 5) == half) ? cand : other;
        float f     = __fdividef(fr, pk);
        if (row > k) {
#pragma unroll
            for (int q = 0; q < 8; ++q) {
                if (c0 + 4*q + 3 >= k) {
                    float4 p = reinterpret_cast<const float4*>(buf)[half * 8 + q];
                    a[4*q]   -= f * p.x;
                    a[4*q+1] -= f * p.y;
                    a[4*q+2] -= f * p.z;
                    a[4*q+3] -= f * p.w;
                }
            }
        }
        if (row == k + 1) {
            float* nb = s_piv + (((k + 1) & 1) << 6);
#pragma unroll
            for (int q = 0; q < 8; ++q)
                reinterpret_cast<float4*>(nb)[half * 8 + q] =
                    make_float4(a[4*q], a[4*q+1], a[4*q+2], a[4*q+3]);
        }
        __syncthreads();
    }
}

// Warp-0 product of the 64 stashed pivots (result on thread 0).
__device__ __forceinline__ double pivot_product(const float* s_pk) {
    const int tid = threadIdx.x;
    double v = 1.0;
    if (tid < 32) {
        v = (double)s_pk[tid] * (double)s_pk[tid + 32];
#pragma unroll
        for (int off = 16; off; off >>= 1)
            v *= __shfl_down_sync(0xffffffffu, v, off);
    }
    return v;
}

// ---------------------------------------------------------------------------
// fp64 single-step engine — only candidate refinement (1 block).
// s_piv MUST be 16B-aligned (double2 access).
// ---------------------------------------------------------------------------
__device__ __forceinline__ double block_det64d(double a[32], double* s_piv, double* s_inv) {
    const int tid  = threadIdx.x;
    const int row  = tid >> 1;
    const int half = tid & 1;
    const int c0   = half << 5;
    if (row == 0) {
#pragma unroll
        for (int q = 0; q < 16; ++q)
            reinterpret_cast<double2*>(s_piv)[half * 16 + q] = make_double2(a[2*q], a[2*q+1]);
        if (tid == 0) s_inv[0] = 1.0 / a[0];
    }
    __syncthreads();
    double det = 1.0;
#pragma unroll
    for (int k = 0; k < 64; ++k) {
        const double* buf = s_piv + ((k & 1) << 6);
        double pk  = buf[k];
        double ipk = s_inv[k & 1];
        if (tid == 0) det *= pk;
        double cand  = a[k & 31];
        double other = __shfl_xor_sync(0xffffffffu, cand, 1);
        double fr    = ((k >> 5) == half) ? cand : other;
        double f     = fr * ipk;
        if (row > k) {
#pragma unroll
            for (int q = 0; q < 16; ++q) {
                if (c0 + 2*q + 1 >= k) {
                    double2 p = reinterpret_cast<const double2*>(buf)[half * 16 + q];
                    a[2*q]   -= f * p.x;
                    a[2*q+1] -= f * p.y;
                }
            }
        }
        if (row == k + 1) {
            double* nb = s_piv + (((k + 1) & 1) << 6);
#pragma unroll
            for (int q = 0; q < 16; ++q)
                reinterpret_cast<double2*>(nb)[half * 16 + q] = make_double2(a[2*q], a[2*q+1]);
            if (((k + 1) >> 5) == half) s_inv[(k + 1) & 1] = 1.0 / a[(k + 1) & 31];
        }
        __syncthreads();
    }
    return det;
}

// ---------------------------------------------------------------------------
// K1 (column-LDL^T engine, 64 threads): per cluster c — state copy, kappa-row
// init, ZZ build, LDL^T of S/n with folded RHS solve -> Vii32, Gamma.
// (round-13 version, measured good)
// ---------------------------------------------------------------------------
__global__ void __launch_bounds__(64, 10)
k1_gamma(const float* __restrict__ z, const float* __restrict__ mu_in,
         const float* __restrict__ S_in, const float* __restrict__ n_in,
         const int* __restrict__ cact) {
    const int c = blockIdx.x;
    const int tid = threadIdx.x;   // 64
    __shared__ __align__(16) float s_col[2][64];
    __shared__ __align__(16) float s_pk[64];
    __shared__ __align__(16) float s_xk[64];
    const float nc = n_in[c];
    const int lane = tid & 31;
    const int h    = tid >> 5;
    const int c0   = h << 5;
    const int rA = lane, rB = lane + 32;
    {
        float m = mu_in[c * ND + tid];
        g_mu[c * ND + tid] = m;
    }
    g_kappa[c * NC + tid]      = f_inf();
    g_kappa[c * NC + tid + 64] = f_inf();
    if (tid == 0) {
        g_n[c] = nc;
        g_active[c] = (c < cact[0]) ? 1 : 0;
        if (c == 0) g_kmin_key = 0x7f800000;
    }
    {
        const float coef = (nc - 1.0f) / nc;
        const float* mc = mu_in + c * ND;
        const float4* Sc4 = reinterpret_cast<const float4*>(S_in + c * ND * ND);
        const float4* mc4 = reinterpret_cast<const float4*>(mc);
        float4* Z4 = reinterpret_cast<float4*>(&g_ZZ[c * ND * ND]);
        for (int t = tid; t < ND * ND / 4; t += 64) {
            float4 s = Sc4[t];
            float4 m = mc4[t & 15];
            float mr = mc[t >> 4];
            Z4[t] = make_float4(coef * s.x + mr * m.x, coef * s.y + mr * m.y,
                                coef * s.z + mr * m.z, coef * s.w + mr * m.w);
        }
    }
    const float invn = 1.0f / nc;
    float aA[32], aB[32];
    {
        const float4* SB = reinterpret_cast<const float4*>(S_in + c * ND * ND + rB * ND + c0);
#pragma unroll
        for (int q = 0; q < 8; ++q) {
            float4 v = SB[q];
            aB[4*q]   = v.x * invn;
            aB[4*q+1] = v.y * invn;
            aB[4*q+2] = v.z * invn;
            aB[4*q+3] = v.w * invn;
        }
    }
    float xA = 0.0f, xB = 0.0f;
    float deuc = 0.0f;
    if (h == 0) {
        const float4* SA = reinterpret_cast<const float4*>(S_in + c * ND * ND + rA * ND);
#pragma unroll
        for (int q = 0; q < 8; ++q) {
            float4 v = SA[q];
            aA[4*q]   = v.x * invn;
            aA[4*q+1] = v.y * invn;
            aA[4*q+2] = v.z * invn;
            aA[4*q+3] = v.w * invn;
        }
        xA = z[rA] - mu_in[c * ND + rA];
        xB = z[rB] - mu_in[c * ND + rB];
        deuc = xA * xA + xB * xB;
#pragma unroll
        for (int off = 16; off; off >>= 1)
            deuc += __shfl_down_sync(0xffffffffu, deuc, off);
        s_col[0][rA] = aA[0];
        s_col[0][rB] = aB[0];
        if (rA == 0) s_xk[0] = xA;
    }
    __syncthreads();
#pragma unroll
    for (int k = 0; k < 64; ++k) {
        const float* cur = s_col[k & 1];
        const float d = cur[k];
        if (tid == 0) s_pk[k] = d;
        const float invd = __fdividef(1.0f, d);
        const float fA = cur[rA] * invd;
        const float fB = cur[rB] * invd;
        const float xk = s_xk[k];
        const bool uA = (h == 0) && (rA > k);
        const bool uB = (rB > k);
#pragma unroll
        for (int q = 0; q < 8; ++q) {
            if (c0 + 4*q + 3 > k) {
                float4 v = *reinterpret_cast<const float4*>(&cur[c0 + 4*q]);
                if (uA) {
                    aA[4*q]   -= fA * v.x;
                    aA[4*q+1] -= fA * v.y;
                    aA[4*q+2] -= fA * v.z;
                    aA[4*q+3] -= fA * v.w;
                }
                if (uB) {
                    aB[4*q]   -= fB * v.x;
                    aB[4*q+1] -= fB * v.y;
                    aB[4*q+2] -= fB * v.z;
                    aB[4*q+3] -= fB * v.w;
                }
            }
        }
        if (h == 0) {
            if (rA > k) xA -= fA * xk;
            if (rB > k) xB -= fB * xk;
        }
        if (k < 63) {
            const int kk = k + 1;
            if ((kk >> 5) == h) {
                float* nxt = s_col[kk & 1];
                const int idx = kk & 31;
                if (h == 0 && rA >= kk) nxt[rA] = aA[idx];
                if (rB >= kk)           nxt[rB] = aB[idx];
            }
            if (h == 0 && rA == (kk & 31))
                s_xk[kk] = (kk < 32) ? xA : xB;
        }
        __syncthreads();
    }
    if (tid < 32) {
        float x0 = s_xk[tid], x1 = s_xk[tid + 32];
        float p0 = s_pk[tid], p1 = s_pk[tid + 32];
        double dmah = (double)(x0 * x0) / (double)p0 + (double)(x1 * x1) / (double)p1;
        double dprod = (double)p0 * (double)p1;
#pragma unroll
        for (int off = 16; off; off >>= 1) {
            dmah  += __shfl_down_sync(0xffffffffu, dmah, off);
            dprod *= __shfl_down_sync(0xffffffffu, dprod, off);
        }
        if (tid == 0) {
            float d2 = (nc < 100.0f) ? deuc : (float)dmah;
            g_Gamma[c] = (c < cact[0]) ? expf(-d2) : 0.0f;
            g_Vii32[c] = (float)dprod;
        }
    }
}

// ---------------------------------------------------------------------------
// K23 (merged k2 + k3_fix), 128 threads, 1 block: argmax Gamma, update/spawn
// (S mutation -> g_Smod + g_modidx), sel flags, then rebuild ZZ + Vii32 for
// the mutated cluster. (verbatim round-9-passing logic)
// ---------------------------------------------------------------------------
__global__ void __launch_bounds__(128, 6)
k23_update_fix(const float* __restrict__ z, const float* __restrict__ S_in,
               const int* __restrict__ cact) {
    const int tid = threadIdx.x;   // 128
    __shared__ __align__(16) float s_ej[64];
    __shared__ __align__(16) float s_piv[128];
    __shared__ __align__(16) float s_pk[64];
    __shared__ int s_j, s_incr, s_c;
    __shared__ float s_nj;
    if (tid < 32) {
        float bv = g_Gamma[tid]; int bi = tid;
#pragma unroll
        for (int t = 1; t < 4; ++t) {
            float v = g_Gamma[tid + 32 * t];
            if (v > bv) { bv = v; bi = tid + 32 * t; }
        }
#pragma unroll
        for (int off = 16; off; off >>= 1) {
            float ov = __shfl_down_sync(0xffffffffu, bv, off);
            int   oi = __shfl_down_sync(0xffffffffu, bi, off);
            if (ov > bv || (ov == bv && oi < bi)) { bv = ov; bi = oi; }
        }
        if (tid == 0) {
            s_j = bi;
            s_incr = (bv > 0.9f) ? 1 : 0;
            s_nj = g_n[bi];
        }
    }
    __syncthreads();
    if (s_incr) {
        const int j = s_j;
        if (tid < 64) s_ej[tid] = z[tid] - g_mu[j * ND + tid];
        __syncthreads();
        if (tid < 64) g_mu[j * ND + tid] += s_ej[tid] / (1.0f + s_nj);
        for (int idx = tid; idx < ND * ND; idx += 128)
            g_Smod[idx] = S_in[j * ND * ND + idx] + s_ej[idx >> 6] * s_ej[idx & 63];
        if (tid == 0) { g_n[j] = s_nj + 1.0f; g_modidx = j; s_c = j; }
    } else {
        const int ca = cact[0];
        if (tid < 64) g_mu[ca * ND + tid] = z[tid];
        for (int idx = tid; idx < ND * ND; idx += 128)
            g_Smod[idx] = ((idx >> 6) == (idx & 63)) ? 1.0f : 0.0f;
        if (tid == 0) { g_n[ca] = 1.0f; g_Gamma[ca] = 1.0f; g_active[ca] = 1;
                        g_modidx = ca; s_c = ca; }
    }
    __syncthreads();
    if (tid < NC)
        g_sel[tid] = (g_Gamma[tid] > 0.225f && g_active[tid]) ? 1 : 0;
    __syncthreads();
    // rebuild ZZ + Vii32 for cluster s_c from g_Smod
    const int c = s_c;
    const float nc   = g_n[c];
    const float coef = (nc - 1.0f) / nc;
    const float invn = 1.0f / nc;
    const float* mc = &g_mu[c * ND];
    const float4* Sc4 = reinterpret_cast<const float4*>(g_Smod);
    const float4* mc4 = reinterpret_cast<const float4*>(mc);
    float4* Z4 = reinterpret_cast<float4*>(&g_ZZ[c * ND * ND]);
    for (int t = tid; t < ND * ND / 4; t += 128) {
        float4 s = Sc4[t];
        float4 m = mc4[t & 15];
        float mr = mc[t >> 4];
        Z4[t] = make_float4(coef * s.x + mr * m.x, coef * s.y + mr * m.y,
                            coef * s.z + mr * m.z, coef * s.w + mr * m.w);
    }
    const int row = tid >> 1;
    const int c0  = (tid & 1) << 5;
    float a[32];
    const float4* Sr = reinterpret_cast<const float4*>(g_Smod + row * ND + c0);
#pragma unroll
    for (int q = 0; q < 8; ++q) {
        float4 v = Sr[q];
        a[4*q]   = v.x * invn;
        a[4*q+1] = v.y * invn;
        a[4*q+2] = v.z * invn;
        a[4*q+3] = v.w * invn;
    }
    __syncthreads();
    block_elim64f(a, s_piv, s_pk);
    double det = pivot_product(s_pk);
    if (tid == 0) g_Vii32[c] = (float)det;
}

// ---------------------------------------------------------------------------
// K4 (SCREEN, LDL^T) — ROUND-13 VERSION (measured good: 137us, passed).
// Triangular grid, 64 threads/block; warp 0 = cols 0-31, warp 1 = cols 32-63
// (warp-uniform predicates); rows (r2, r2+32). Hoisted reciprocal, early
// publish of column k+1, warp-0 retirement for k >= 32.
// ---------------------------------------------------------------------------
__global__ void __launch_bounds__(64, 10)
k4_pairs() {
    const int b = blockIdx.x;          // 0 .. NPAIRS-1
    int i = (int)((float)NC - 0.5f
                  - sqrtf(((float)NC - 0.5f) * ((float)NC - 0.5f) - 2.0f * (float)b));
    if (i < 0) i = 0;
    if (i > NC - 2) i = NC - 2;
    while (i > 0 && (i * (2 * NC - i - 1)) / 2 > b) --i;
    while (((i + 1) * (2 * NC - i - 2)) / 2 <= b) ++i;
    const int j = b - (i * (2 * NC - i - 1)) / 2 + i + 1;
    const int tid = threadIdx.x;   // 64
    if (!g_sel[i] || !g_sel[j]) return;     // g_kappa pre-initialized to inf
    __shared__ __align__(16) float s_col[2][64];
    __shared__ __align__(16) float s_pk[64];
    __shared__ __align__(16) float s_invd[64];
    __shared__ __align__(16) float s_muij[64];
    const float ni = g_n[i], nj = g_n[j];
    const float nij = ni + nj;
    s_muij[tid] = (ni * g_mu[i * ND + tid] + nj * g_mu[j * ND + tid]) / nij;
    __syncthreads();
    const float invs = 1.0f / (nij - 1.0f);
    const int r2 = tid & 31;
    const int h  = tid >> 5;          // warp-uniform
    const int c0 = h << 5;
    const int rA = r2, rB = r2 + 32;
    float aA[32], aB[32];
    {
        const float mrB = s_muij[rB];
        const float4* zi4 = reinterpret_cast<const float4*>(&g_ZZ[i * ND * ND + rB * ND + c0]);
        const float4* zj4 = reinterpret_cast<const float4*>(&g_ZZ[j * ND * ND + rB * ND + c0]);
#pragma unroll
        for (int q = 0; q < 8; ++q) {
            float4 x = zi4[q], y = zj4[q];
            aB[4*q]   = (x.x + y.x - mrB * s_muij[c0 + 4*q])     * invs;
            aB[4*q+1] = (x.y + y.y - mrB * s_muij[c0 + 4*q + 1]) * invs;
            aB[4*q+2] = (x.z + y.z - mrB * s_muij[c0 + 4*q + 2]) * invs;
            aB[4*q+3] = (x.w + y.w - mrB * s_muij[c0 + 4*q + 3]) * invs;
        }
    }
    if (h == 0) {
        const float mrA = s_muij[rA];
        const float4* zi4 = reinterpret_cast<const float4*>(&g_ZZ[i * ND * ND + rA * ND]);
        const float4* zj4 = reinterpret_cast<const float4*>(&g_ZZ[j * ND * ND + rA * ND]);
#pragma unroll
        for (int q = 0; q < 8; ++q) {
            float4 x = zi4[q], y = zj4[q];
            aA[4*q]   = (x.x + y.x - mrA * s_muij[4*q])     * invs;
            aA[4*q+1] = (x.y + y.y - mrA * s_muij[4*q + 1]) * invs;
            aA[4*q+2] = (x.z + y.z - mrA * s_muij[4*q + 2]) * invs;
            aA[4*q+3] = (x.w + y.w - mrA * s_muij[4*q + 3]) * invs;
        }
        s_col[0][rA] = aA[0];
        s_col[0][rB] = aB[0];
        if (rA == 0) s_invd[0] = __fdividef(1.0f, aA[0]);
    }
    __syncthreads();
    // ---- phase 1: k = 0..31, full block ----
#pragma unroll
    for (int k = 0; k < 32; ++k) {
        const float* cur = s_col[k & 1];
        const float invd = s_invd[k];
        if (tid == 0) s_pk[k] = cur[k];
        const float fA = cur[rA] * invd;
        const float fB = cur[rB] * invd;
        // early publish of column k+1 (+ its reciprocal)
        {
            const int kk = k + 1;
            if ((kk >> 5) == h) {          // h=0 for kk<32; kk==32 -> h=1
                float* nxt = s_col[kk & 1];
                const int idx = kk & 31;
                const float ck = cur[kk];
                if (h == 0) {
                    if (rA >= kk) {
                        float val = aA[idx] - fA * ck;
                        nxt[rA] = val;
                        if (rA == kk) s_invd[kk] = __fdividef(1.0f, val);
                    }
                    {   // rB (= r2+32) always >= 32 > kk here
                        float val = aB[idx] - fB * ck;
                        nxt[rB] = val;
                    }
                } else {                    // kk == 32 only
                    float val = aB[idx] - fB * ck;   // idx = 0
                    nxt[rB] = val;                   // rB >= 32 == kk
                    if (rB == kk) s_invd[kk] = __fdividef(1.0f, val);
                }
            }
        }
        // bulk chunk updates (in the shadow of the publish)
        const bool uA = (h == 0) && (rA > k);
        const bool uB = (rB > k);
#pragma unroll
        for (int q = 0; q < 8; ++q) {
            if (c0 + 4*q + 3 > k) {        // warp-uniform live-chunk test
                float4 v = *reinterpret_cast<const float4*>(&cur[c0 + 4*q]);
                if (uA) {
                    aA[4*q]   -= fA * v.x;
                    aA[4*q+1] -= fA * v.y;
                    aA[4*q+2] -= fA * v.z;
                    aA[4*q+3] -= fA * v.w;
                }
                if (uB) {
                    aB[4*q]   -= fB * v.x;
                    aB[4*q+1] -= fB * v.y;
                    aB[4*q+2] -= fB * v.z;
                    aB[4*q+3] -= fB * v.w;
                }
            }
        }
        __syncthreads();
    }
    // ---- phase 2: k = 32..63, warp 1 only (warp 0 provably idle) ----
    if (h == 1) {
#pragma unroll
        for (int k = 32; k < 64; ++k) {
            const float* cur = s_col[k & 1];
            const float invd = s_invd[k];
            if (tid == 32) s_pk[k] = cur[k];
            const float fB = cur[rB] * invd;
            if (k < 63) {
                const int kk = k + 1;      // always in half 1
                float* nxt = s_col[kk & 1];
                const int idx = kk & 31;
                const float ck = cur[kk];
                if (rB >= kk) {
                    float val = aB[idx] - fB * ck;
                    nxt[rB] = val;
                    if (rB == kk) s_invd[kk] = __fdividef(1.0f, val);
                }
            }
            if (rB > k) {
#pragma unroll
                for (int q = 0; q < 8; ++q) {
                    if (32 + 4*q + 3 > k) {
                        float4 v = *reinterpret_cast<const float4*>(&cur[32 + 4*q]);
                        aB[4*q]   -= fB * v.x;
                        aB[4*q+1] -= fB * v.y;
                        aB[4*q+2] -= fB * v.z;
                        aB[4*q+3] -= fB * v.w;
                    }
                }
            }
            __syncwarp();
        }
    }
    __syncthreads();
    double det = pivot_product(s_pk);
    if (tid == 0) {
        float kap = vij_valid(det) ? ((float)(det / (double)(g_Vii32[i] + g_Vii32[j])))
                                   : f_inf();
        g_kappa[i * NC + j] = kap;
        if (kap < f_inf()) atomicMin(&g_kmin_key, f2key(kap));
    }
}

// ---------------------------------------------------------------------------
// K5 (fused select + fp64 refine + merge + output), 1 block x 128 threads.
// kmin is already in g_kmin_key (k4 atomics). Candidates (<=32, typically 1)
// are refined with the fp64 engine; argmin uses first-flat-index ties.
// ---------------------------------------------------------------------------
__global__ void k5_final(float* __restrict__ out) {
    const int tid = threadIdx.x;   // 128
    __shared__ __align__(16) double s_piv[128];   // double2 access -> 16B align
    __shared__ __align__(16) double s_muij[64];
    __shared__ __align__(16) double sh_kv[32];
    __shared__ double s_inv[2];
    __shared__ int    sh_ncand;
    __shared__ int    sh_cand[32];
    __shared__ int s_mi, s_mj, s_do;
    __shared__ float s_nmi, s_nmj;
    if (tid == 0) sh_ncand = 0;
    __syncthreads();
    const float kmin = key2f(g_kmin_key);
    if (kmin < 3.0e38f) {
        const float thr = kmin + (fabsf(kmin) * 1e-3f + 1e-30f);
        for (int b = tid; b < NC * NC; b += 128) {
            if (g_kappa[b] <= thr) {
                int p = atomicAdd(&sh_ncand, 1);
                if (p < 32) sh_cand[p] = b;
            }
        }
    }
    __syncthreads();
    const int ncand = min(sh_ncand, 32);
    for (int cidx = 0; cidx < ncand; ++cidx) {
        const int flat = sh_cand[cidx];
        const int i = flat >> 7;
        const int j = flat & (NC - 1);
        const double ni = (double)g_n[i], nj = (double)g_n[j];
        const double nij = ni + nj;
        if (tid < 64)
            s_muij[tid] = (ni * (double)g_mu[i * ND + tid]
                         + nj * (double)g_mu[j * ND + tid]) / nij;
        __syncthreads();
        const double invs = 1.0 / (nij - 1.0);
        const int row = tid >> 1;
        const int c0  = (tid & 1) << 5;
        const double mr = s_muij[row];
        const float* zi = &g_ZZ[i * ND * ND + row * ND + c0];
        const float* zj = &g_ZZ[j * ND * ND + row * ND + c0];
        double a[32];
#pragma unroll
        for (int q = 0; q < 32; ++q)
            a[q] = ((double)zi[q] + (double)zj[q] - mr * s_muij[c0 + q]) * invs;
        double det = block_det64d(a, s_piv, s_inv);
        if (tid == 0)
            sh_kv[cidx] = vij_valid(det)
                              ? (det / ((double)g_Vii32[i] + (double)g_Vii32[j]))
                              : d_inf();
        __syncthreads();
    }
    if (tid == 0) {
        double bv = d_inf(); int bi = 0x7fffffff;
        for (int c2 = 0; c2 < ncand; ++c2) {
            double v = sh_kv[c2]; int fi = sh_cand[c2];
            if (v < bv || (v == bv && fi < bi)) { bv = v; bi = fi; }
        }
        s_do = (bv < 0.9) ? 1 : 0;
        s_mi = bi >> 7;
        s_mj = bi & (NC - 1);
        if (s_do) { s_nmi = g_n[s_mi]; s_nmj = g_n[s_mj]; }
    }
    __syncthreads();
    if (s_do) {
        if (tid < 64) {
            const int mi = s_mi, mj = s_mj;
            g_mu[mi * ND + tid] =
                (s_nmi * g_mu[mi * ND + tid] + s_nmj * g_mu[mj * ND + tid]) / (s_nmi + s_nmj);
        }
        if (tid == 0) g_active[s_mj] = 0;
    }
    __syncthreads();
    for (int idx = tid; idx < NC * ND; idx += 128)
        out[idx] = g_active[idx >> 6] ? g_mu[idx] : 0.0f;
}

// ---------------------------------------------------------------------------
extern "C" void kernel_launch(void* const* d_in, const int* in_sizes, int n_in,
                              void* d_out, int out_size) {
    const float* z  = (const float*)d_in[0];
    const float* mu = (const float*)d_in[1];
    const float* S  = (const float*)d_in[2];
    const float* n  = (const float*)d_in[3];
    const int*   ca = (const int*)d_in[4];
    float* out = (float*)d_out;

    k1_gamma<<<NC, 64>>>(z, mu, S, n, ca);
    k23_update_fix<<<1, 128>>>(z, S, ca);
    k4_pairs<<<NPAIRS, 64>>>();
    k5_final<<<1, 128>>>(out);
}